// round 2
// baseline (speedup 1.0000x reference)
#include <cuda_runtime.h>
#include <math.h>

// Problem constants
#define D_MODEL 1024
#define NHEAD   16
#define DH      64
#define SEQ     2048
#define BATCH   4
#define MTOT    (BATCH*SEQ)          // 8192

// ---------------------------------------------------------------------------
// Scratch (device globals; no allocation anywhere)
// ---------------------------------------------------------------------------
__device__ float g_Q[BATCH*NHEAD*SEQ*DH];   // [B,H,S,Dh]
__device__ float g_K[BATCH*NHEAD*SEQ*DH];
__device__ float g_V[BATCH*NHEAD*SEQ*DH];
__device__ float g_T[MTOT*D_MODEL];         // attention output, [B,S,H*Dh] row-major

// ---------------------------------------------------------------------------
// SGEMM (NT): C[m,n] = sum_k A[m,k] * W[n,k]
//   A: [8192,1024] row-major (K contiguous), W: [1024,1024] row-major (K contiguous)
// mode 0/1/2: write g_Q/g_K/g_V in [B,H,S,Dh] layout
// mode 3:     A is ignored -> uses g_T; writes C_ext row-major [M,N]
// Tile: BM=128, BN=128, BK=8, 256 threads, 8x8 per thread.
// ---------------------------------------------------------------------------
__global__ __launch_bounds__(256) void sgemm_nt(const float* __restrict__ A_ext,
                                                const float* __restrict__ W,
                                                float* __restrict__ C_ext,
                                                int mode)
{
    const int K = 1024;
    __shared__ float As[8][128];
    __shared__ float Bs[8][128];

    const float* A = (mode == 3) ? g_T : A_ext;

    int tid = threadIdx.x;            // 0..255
    int m0  = blockIdx.y * 128;
    int n0  = blockIdx.x * 128;

    int lRow = tid >> 1;              // 0..127
    int lCol = (tid & 1) << 2;        // 0 or 4

    const float* Ag = A + (size_t)(m0 + lRow) * K + lCol;
    const float* Wg = W + (size_t)(n0 + lRow) * K + lCol;

    int tx = tid & 15;                // n-group
    int ty = tid >> 4;                // m-group

    float acc[8][8];
#pragma unroll
    for (int i = 0; i < 8; ++i)
#pragma unroll
        for (int j = 0; j < 8; ++j) acc[i][j] = 0.f;

    for (int k0 = 0; k0 < K; k0 += 8) {
        float4 av = *(const float4*)(Ag + k0);
        float4 wv = *(const float4*)(Wg + k0);
        As[lCol + 0][lRow] = av.x; As[lCol + 1][lRow] = av.y;
        As[lCol + 2][lRow] = av.z; As[lCol + 3][lRow] = av.w;
        Bs[lCol + 0][lRow] = wv.x; Bs[lCol + 1][lRow] = wv.y;
        Bs[lCol + 2][lRow] = wv.z; Bs[lCol + 3][lRow] = wv.w;
        __syncthreads();

#pragma unroll
        for (int k = 0; k < 8; ++k) {
            float4 a0 = *(const float4*)&As[k][ty * 8];
            float4 a1 = *(const float4*)&As[k][ty * 8 + 4];
            float4 b0 = *(const float4*)&Bs[k][tx * 8];
            float4 b1 = *(const float4*)&Bs[k][tx * 8 + 4];
            float ar[8] = {a0.x, a0.y, a0.z, a0.w, a1.x, a1.y, a1.z, a1.w};
            float br[8] = {b0.x, b0.y, b0.z, b0.w, b1.x, b1.y, b1.z, b1.w};
#pragma unroll
            for (int i = 0; i < 8; ++i)
#pragma unroll
                for (int j = 0; j < 8; ++j)
                    acc[i][j] = fmaf(ar[i], br[j], acc[i][j]);
        }
        __syncthreads();
    }

    // Epilogue
    if (mode == 3) {
#pragma unroll
        for (int i = 0; i < 8; ++i) {
            int m = m0 + ty * 8 + i;
#pragma unroll
            for (int jv = 0; jv < 8; jv += 4) {
                int n = n0 + tx * 8 + jv;
                float4 v = make_float4(acc[i][jv], acc[i][jv+1], acc[i][jv+2], acc[i][jv+3]);
                *(float4*)&C_ext[(size_t)m * D_MODEL + n] = v;
            }
        }
    } else {
        float* dst = (mode == 0) ? g_Q : (mode == 1) ? g_K : g_V;
#pragma unroll
        for (int i = 0; i < 8; ++i) {
            int m = m0 + ty * 8 + i;
            int b = m >> 11;            // / 2048
            int s = m & 2047;
#pragma unroll
            for (int jv = 0; jv < 8; jv += 4) {
                int n = n0 + tx * 8 + jv;
                int h = n >> 6;         // / 64
                int d = n & 63;
                float4 v = make_float4(acc[i][jv], acc[i][jv+1], acc[i][jv+2], acc[i][jv+3]);
                size_t off = (((size_t)(b * NHEAD + h)) * SEQ + s) * DH + d;
                *(float4*)&dst[off] = v;
            }
        }
    }
}

// ---------------------------------------------------------------------------
// Flash attention, fp32, causal.
// grid: (SEQ/64, B*H); block: 256 threads laid out 16(tx: key/dim groups) x 16(ty: query groups)
// Each thread owns a 4x4 sub-tile. Online softmax; causal tiles kt>qt skipped.
// smem (dynamic): Qst[64d][68q], Kst[64d][68k], Vs[64k][68d], Pst[64k][68q]
// ---------------------------------------------------------------------------
#define APAD 68
#define ASMEM_BYTES (4 * 64 * APAD * 4)

__global__ __launch_bounds__(256) void attn_kernel()
{
    extern __shared__ float sm[];
    float* Qst = sm;
    float* Kst = sm + 64 * APAD;
    float* Vs  = sm + 2 * 64 * APAD;
    float* Pst = sm + 3 * 64 * APAD;

    int tid = threadIdx.x;
    int tx  = tid & 15;     // key-group / dim-group
    int ty  = tid >> 4;     // query-group
    int qt  = blockIdx.x;   // query tile (64 queries)
    int bh  = blockIdx.y;   // b*16 + h

    const float* Qb = g_Q + ((size_t)bh * SEQ + qt * 64) * DH;

    // Load Q tile transposed: Qst[d][q]
#pragma unroll
    for (int r = 0; r < 4; ++r) {
        int row = r * 16 + ty;          // query 0..63
        int c4  = tx * 4;               // dim
        float4 v = *(const float4*)(Qb + row * DH + c4);
        Qst[(c4 + 0) * APAD + row] = v.x;
        Qst[(c4 + 1) * APAD + row] = v.y;
        Qst[(c4 + 2) * APAD + row] = v.z;
        Qst[(c4 + 3) * APAD + row] = v.w;
    }

    float o[4][4];
    float mrow[4], lrow[4];
#pragma unroll
    for (int i = 0; i < 4; ++i) {
        mrow[i] = -1e30f; lrow[i] = 0.f;
#pragma unroll
        for (int j = 0; j < 4; ++j) o[i][j] = 0.f;
    }

    const float scale = 0.125f;   // 1/sqrt(64)

    for (int kt = 0; kt <= qt; ++kt) {
        // Load K (transposed) and V (natural) tiles
        const float* Kb = g_K + ((size_t)bh * SEQ + kt * 64) * DH;
        const float* Vb = g_V + ((size_t)bh * SEQ + kt * 64) * DH;
#pragma unroll
        for (int r = 0; r < 4; ++r) {
            int row = r * 16 + ty;
            int c4  = tx * 4;
            float4 kv = *(const float4*)(Kb + row * DH + c4);
            Kst[(c4 + 0) * APAD + row] = kv.x;
            Kst[(c4 + 1) * APAD + row] = kv.y;
            Kst[(c4 + 2) * APAD + row] = kv.z;
            Kst[(c4 + 3) * APAD + row] = kv.w;
            float4 vv = *(const float4*)(Vb + row * DH + c4);
            *(float4*)&Vs[row * APAD + c4] = vv;
        }
        __syncthreads();

        // S = scale * Q K^T  (4x4 per thread)
        float s[4][4];
#pragma unroll
        for (int i = 0; i < 4; ++i)
#pragma unroll
            for (int j = 0; j < 4; ++j) s[i][j] = 0.f;

#pragma unroll 8
        for (int d = 0; d < 64; ++d) {
            float4 qv = *(const float4*)&Qst[d * APAD + ty * 4];
            float4 kv = *(const float4*)&Kst[d * APAD + tx * 4];
            float qa[4] = {qv.x, qv.y, qv.z, qv.w};
            float ka[4] = {kv.x, kv.y, kv.z, kv.w};
#pragma unroll
            for (int i = 0; i < 4; ++i)
#pragma unroll
                for (int j = 0; j < 4; ++j)
                    s[i][j] = fmaf(qa[i], ka[j], s[i][j]);
        }

        // scale + causal mask (diagonal tile only)
        if (kt == qt) {
#pragma unroll
            for (int i = 0; i < 4; ++i)
#pragma unroll
                for (int j = 0; j < 4; ++j)
                    s[i][j] = ((tx * 4 + j) > (ty * 4 + i)) ? -1e30f : s[i][j] * scale;
        } else {
#pragma unroll
            for (int i = 0; i < 4; ++i)
#pragma unroll
                for (int j = 0; j < 4; ++j) s[i][j] *= scale;
        }

        // online softmax update (row reductions over the 16 tx lanes)
        float p[4][4];
#pragma unroll
        for (int i = 0; i < 4; ++i) {
            float mt = s[i][0];
            mt = fmaxf(mt, s[i][1]); mt = fmaxf(mt, s[i][2]); mt = fmaxf(mt, s[i][3]);
#pragma unroll
            for (int off = 8; off >= 1; off >>= 1)
                mt = fmaxf(mt, __shfl_xor_sync(0xffffffffu, mt, off, 16));
            float mnew = fmaxf(mrow[i], mt);
            float alpha = __expf(mrow[i] - mnew);
            float lt = 0.f;
#pragma unroll
            for (int j = 0; j < 4; ++j) {
                p[i][j] = __expf(s[i][j] - mnew);
                lt += p[i][j];
            }
#pragma unroll
            for (int off = 8; off >= 1; off >>= 1)
                lt += __shfl_xor_sync(0xffffffffu, lt, off, 16);
            lrow[i] = lrow[i] * alpha + lt;
            mrow[i] = mnew;
#pragma unroll
            for (int j = 0; j < 4; ++j) o[i][j] *= alpha;
        }

        // write P transposed: Pst[k][q]
#pragma unroll
        for (int i = 0; i < 4; ++i)
#pragma unroll
            for (int j = 0; j < 4; ++j)
                Pst[(tx * 4 + j) * APAD + ty * 4 + i] = p[i][j];
        __syncthreads();

        // O += P @ V : thread owns queries ty*4.., dims tx*4..
#pragma unroll 8
        for (int k = 0; k < 64; ++k) {
            float4 pv = *(const float4*)&Pst[k * APAD + ty * 4];
            float4 vv = *(const float4*)&Vs[k * APAD + tx * 4];
            float pa[4] = {pv.x, pv.y, pv.z, pv.w};
            float va[4] = {vv.x, vv.y, vv.z, vv.w};
#pragma unroll
            for (int i = 0; i < 4; ++i)
#pragma unroll
                for (int j = 0; j < 4; ++j)
                    o[i][j] = fmaf(pa[i], va[j], o[i][j]);
        }
        __syncthreads();
    }

    // normalize + store to g_T [B,S,H*Dh] row-major
    int b = bh >> 4;
    int h = bh & 15;
#pragma unroll
    for (int i = 0; i < 4; ++i) {
        float inv = 1.f / lrow[i];
        int q = qt * 64 + ty * 4 + i;
        float4 v = make_float4(o[i][0] * inv, o[i][1] * inv, o[i][2] * inv, o[i][3] * inv);
        *(float4*)&g_T[((size_t)(b * SEQ + q)) * D_MODEL + h * 64 + tx * 4] = v;
    }
}

// ---------------------------------------------------------------------------
// Launch
// ---------------------------------------------------------------------------
extern "C" void kernel_launch(void* const* d_in, const int* in_sizes, int n_in,
                              void* d_out, int out_size)
{
    const float* X  = (const float*)d_in[0];
    const float* WQ = (const float*)d_in[1];
    const float* WK = (const float*)d_in[2];
    const float* WV = (const float*)d_in[3];
    const float* WO = (const float*)d_in[4];
    float* out = (float*)d_out;

    dim3 ggrid(D_MODEL / 128, MTOT / 128);   // (8, 64)
    sgemm_nt<<<ggrid, 256>>>(X, WQ, nullptr, 0);
    sgemm_nt<<<ggrid, 256>>>(X, WK, nullptr, 1);
    sgemm_nt<<<ggrid, 256>>>(X, WV, nullptr, 2);

    cudaFuncSetAttribute(attn_kernel, cudaFuncAttributeMaxDynamicSharedMemorySize, ASMEM_BYTES);
    dim3 agrid(SEQ / 64, BATCH * NHEAD);     // (32, 64)
    attn_kernel<<<agrid, 256, ASMEM_BYTES>>>();

    sgemm_nt<<<ggrid, 256>>>(nullptr, WO, out, 3);
}

// round 4
// speedup vs baseline: 1.0611x; 1.0611x over previous
#include <cuda_runtime.h>
#include <cuda_bf16.h>
#include <stdint.h>
#include <math.h>

// Problem constants
#define D_MODEL 1024
#define NHEAD   16
#define DH      64
#define SEQ     2048
#define BATCH   4
#define MTOT    (BATCH*SEQ)          // 8192
#define KE      2048                 // split storage: [hi(1024) | lo(1024)]

// ---------------------------------------------------------------------------
// Scratch (device globals; no allocation anywhere)
// ---------------------------------------------------------------------------
__device__ float g_Q[BATCH*NHEAD*SEQ*DH];   // [B,H,S,Dh] fp32
__device__ float g_K[BATCH*NHEAD*SEQ*DH];
__device__ float g_V[BATCH*NHEAD*SEQ*DH];
__device__ float g_T[MTOT*D_MODEL];         // attention output, [B,S,H*Dh] fp32

__device__ __nv_bfloat16 g_Xext[(size_t)MTOT*KE];       // X split hi|lo
__device__ __nv_bfloat16 g_Wext[4][(size_t)D_MODEL*KE]; // WQ,WK,WV,WO split
__device__ __nv_bfloat16 g_Text[(size_t)MTOT*KE];       // attn-out split

// ---------------------------------------------------------------------------
// Helpers (portable PTX only: cp.async, ldmatrix, mma.sync — all sm_80+)
// ---------------------------------------------------------------------------
__device__ __forceinline__ uint32_t smem_u32(const void* p) {
    uint32_t a;
    asm("{ .reg .u64 t; cvta.to.shared.u64 t, %1; cvt.u32.u64 %0, t; }" : "=r"(a) : "l"(p));
    return a;
}
__device__ __forceinline__ void cp16(uint32_t saddr, const void* gaddr) {
    asm volatile("cp.async.cg.shared.global [%0], [%1], 16;" :: "r"(saddr), "l"(gaddr));
}
__device__ __forceinline__ void ldsm_x4(uint32_t& r0, uint32_t& r1, uint32_t& r2, uint32_t& r3, uint32_t addr) {
    asm volatile("ldmatrix.sync.aligned.m8n8.x4.shared.b16 {%0,%1,%2,%3}, [%4];"
                 : "=r"(r0), "=r"(r1), "=r"(r2), "=r"(r3) : "r"(addr));
}
__device__ __forceinline__ void mma_bf16(float& c0, float& c1, float& c2, float& c3,
                                         uint32_t a0, uint32_t a1, uint32_t a2, uint32_t a3,
                                         uint32_t b0, uint32_t b1) {
    asm volatile("mma.sync.aligned.m16n8k16.row.col.f32.bf16.bf16.f32 "
                 "{%0,%1,%2,%3}, {%4,%5,%6,%7}, {%8,%9}, {%0,%1,%2,%3};"
                 : "+f"(c0), "+f"(c1), "+f"(c2), "+f"(c3)
                 : "r"(a0), "r"(a1), "r"(a2), "r"(a3), "r"(b0), "r"(b1));
}
#define SWZ(x) ((x) ^ (((x) >> 3) & 0x70))

// ---------------------------------------------------------------------------
// fp32 -> bf16 split (hi|lo) converter.
// mode 0..3: weights -> g_Wext[mode];  mode 4: X -> g_Xext;  mode 5: g_T -> g_Text
// ---------------------------------------------------------------------------
__global__ void convert_split(const float* __restrict__ src, int n, int mode)
{
    __nv_bfloat16* dst = (mode < 4) ? g_Wext[mode] : (mode == 4 ? g_Xext : g_Text);
    const float* s = (mode == 5) ? g_T : src;
    for (int i = blockIdx.x * blockDim.x + threadIdx.x; i < n; i += gridDim.x * blockDim.x) {
        int r = i >> 10, c = i & 1023;
        float x = s[i];
        __nv_bfloat16 hi = __float2bfloat16(x);
        float lo = x - __bfloat162float(hi);
        dst[(size_t)r * KE + c]        = hi;
        dst[(size_t)r * KE + 1024 + c] = __float2bfloat16(lo);
    }
}

// ---------------------------------------------------------------------------
// bf16 tensor-core GEMM (mma.sync) with hi/lo compensation.
// C[m,n] = sum_k A[m,k]*W[n,k] via 3 bf16 term passes: (Ah,Wh),(Ah,Wl),(Al,Wh)
// = 48 K-chunks of 64, accumulated in fp32 registers.
// Block tile M=128, N=128, BK=64. 256 threads = 8 warps (4m x 2n), warp 32x64.
// Double-buffered cp.async; SW128-swizzled smem; ldmatrix.x4 operand loads.
// mode 0/1/2: A=g_Xext, W=g_Wext[mode], dst=g_Q/K/V in [B,H,S,Dh]
// mode 3:     A=g_Text, W=g_Wext[3],    dst=outp row-major [8192,1024]
// ---------------------------------------------------------------------------
#define TILE_BYTES 16384            // 128 rows x 128B (64 bf16)
#define GSM_BYTES  (4 * TILE_BYTES) // A0,B0,A1,B1

__global__ __launch_bounds__(256) void gemm_mma(float* __restrict__ outp, int mode)
{
    extern __shared__ char smem[];
    uint32_t sb = smem_u32(smem);
    const uint32_t aS[2] = {sb,                  sb + 2 * TILE_BYTES};
    const uint32_t bS[2] = {sb + TILE_BYTES,     sb + 3 * TILE_BYTES};

    int tid = threadIdx.x;
    int wid = tid >> 5;
    int lid = tid & 31;
    int wm = wid >> 1;              // 0..3  (32 rows each)
    int wn = wid & 1;               // 0..1  (64 cols each)
    int m0 = blockIdx.y * 128;
    int n0 = blockIdx.x * 128;

    const __nv_bfloat16* A = (mode == 3) ? g_Text : g_Xext;
    const __nv_bfloat16* W = g_Wext[mode];
    const char* Abase = (const char*)(A + (size_t)m0 * KE);
    const char* Wbase = (const char*)(W + (size_t)n0 * KE);

    float acc[2][8][4];
#pragma unroll
    for (int mt = 0; mt < 2; ++mt)
#pragma unroll
        for (int j = 0; j < 8; ++j)
#pragma unroll
            for (int v = 0; v < 4; ++v) acc[mt][j][v] = 0.f;

    // Per-thread loader coords (4 segs of 16B per matrix per chunk)
    int lrow[4], lcol[4];
    uint32_t lso[4];
#pragma unroll
    for (int t = 0; t < 4; ++t) {
        int idx = tid + t * 256;
        lrow[t] = idx >> 3;
        lcol[t] = (idx & 7) * 16;
        lso[t]  = SWZ((uint32_t)(lrow[t] * 128 + lcol[t]));
    }

    // chunk i (0..47): term = i>>4, c = i&15
    // ka = (term==2 ? 1024 : 0) + c*64 ; kb = (term==1 ? 1024 : 0) + c*64  (elements)
    {
        // prefetch chunk 0 (ka = kb = 0)
#pragma unroll
        for (int t = 0; t < 4; ++t) {
            size_t g = (size_t)lrow[t] * 4096 + lcol[t];
            cp16(aS[0] + lso[t], Abase + g);
            cp16(bS[0] + lso[t], Wbase + g);
        }
        asm volatile("cp.async.commit_group;" ::: "memory");
    }

    for (int i = 0; i < 48; ++i) {
        int cur = i & 1;
        if (i + 1 < 48) {
            int j = i + 1, tterm = j >> 4, c = j & 15;
            int ka = ((tterm == 2) ? 1024 : 0) + c * 64;
            int kb = ((tterm == 1) ? 1024 : 0) + c * 64;
            const char* ag = Abase + (size_t)ka * 2;
            const char* bg = Wbase + (size_t)kb * 2;
#pragma unroll
            for (int t = 0; t < 4; ++t) {
                size_t g = (size_t)lrow[t] * 4096 + lcol[t];
                cp16(aS[cur ^ 1] + lso[t], ag + g);
                cp16(bS[cur ^ 1] + lso[t], bg + g);
            }
            asm volatile("cp.async.commit_group;" ::: "memory");
            asm volatile("cp.async.wait_group 1;" ::: "memory");
        } else {
            asm volatile("cp.async.wait_group 0;" ::: "memory");
        }
        __syncthreads();

        // Compute on buffer `cur`: 4 k16 steps
#pragma unroll
        for (int ks = 0; ks < 4; ++ks) {
            int kb2 = ks * 32;   // byte offset within 128B row
            uint32_t a[2][4];
#pragma unroll
            for (int mt = 0; mt < 2; ++mt) {
                int row = wm * 32 + mt * 16 + (lid & 15);
                uint32_t addr = aS[cur] + SWZ((uint32_t)(row * 128 + kb2 + ((lid >> 4) * 16)));
                ldsm_x4(a[mt][0], a[mt][1], a[mt][2], a[mt][3], addr);
            }
            uint32_t b[4][4];
#pragma unroll
            for (int ng = 0; ng < 4; ++ng) {
                int row = wn * 64 + ng * 16 + ((lid >> 4) << 3) + (lid & 7);
                uint32_t addr = bS[cur] + SWZ((uint32_t)(row * 128 + kb2 + (((lid >> 3) & 1) * 16)));
                ldsm_x4(b[ng][0], b[ng][1], b[ng][2], b[ng][3], addr);
            }
#pragma unroll
            for (int mt = 0; mt < 2; ++mt)
#pragma unroll
                for (int ng = 0; ng < 4; ++ng) {
                    mma_bf16(acc[mt][ng*2+0][0], acc[mt][ng*2+0][1], acc[mt][ng*2+0][2], acc[mt][ng*2+0][3],
                             a[mt][0], a[mt][1], a[mt][2], a[mt][3], b[ng][0], b[ng][1]);
                    mma_bf16(acc[mt][ng*2+1][0], acc[mt][ng*2+1][1], acc[mt][ng*2+1][2], acc[mt][ng*2+1][3],
                             a[mt][0], a[mt][1], a[mt][2], a[mt][3], b[ng][2], b[ng][3]);
                }
        }
        __syncthreads();
    }

    // Epilogue: lane (row r = lane>>2 [+8], cols 2*(lane&3)+{0,1})
#pragma unroll
    for (int mt = 0; mt < 2; ++mt) {
#pragma unroll
        for (int j = 0; j < 8; ++j) {
            int row = m0 + wm * 32 + mt * 16 + (lid >> 2);
            int col = n0 + wn * 64 + j * 8 + ((lid & 3) << 1);
            float2 v0 = make_float2(acc[mt][j][0], acc[mt][j][1]);
            float2 v1 = make_float2(acc[mt][j][2], acc[mt][j][3]);
            if (mode == 3) {
                *(float2*)(outp + (size_t)row * D_MODEL + col)       = v0;
                *(float2*)(outp + (size_t)(row + 8) * D_MODEL + col) = v1;
            } else {
                float* base = (mode == 0) ? g_Q : (mode == 1) ? g_K : g_V;
                int h = col >> 6, d0 = col & 63;
                int b0_ = row >> 11, s0 = row & 2047;
                int r1 = row + 8;
                int b1_ = r1 >> 11, s1 = r1 & 2047;
                *(float2*)(base + (((size_t)(b0_ * NHEAD + h)) * SEQ + s0) * DH + d0) = v0;
                *(float2*)(base + (((size_t)(b1_ * NHEAD + h)) * SEQ + s1) * DH + d0) = v1;
            }
        }
    }
}

// ---------------------------------------------------------------------------
// Flash attention, fp32, causal (unchanged; known-good from R1).
// ---------------------------------------------------------------------------
#define APAD 68
#define ASMEM_BYTES (4 * 64 * APAD * 4)

__global__ __launch_bounds__(256) void attn_kernel()
{
    extern __shared__ float sm[];
    float* Qst = sm;
    float* Kst = sm + 64 * APAD;
    float* Vs  = sm + 2 * 64 * APAD;
    float* Pst = sm + 3 * 64 * APAD;

    int tid = threadIdx.x;
    int tx  = tid & 15;
    int ty  = tid >> 4;
    int qt  = blockIdx.x;
    int bh  = blockIdx.y;

    const float* Qb = g_Q + ((size_t)bh * SEQ + qt * 64) * DH;

#pragma unroll
    for (int r = 0; r < 4; ++r) {
        int row = r * 16 + ty;
        int c4  = tx * 4;
        float4 v = *(const float4*)(Qb + row * DH + c4);
        Qst[(c4 + 0) * APAD + row] = v.x;
        Qst[(c4 + 1) * APAD + row] = v.y;
        Qst[(c4 + 2) * APAD + row] = v.z;
        Qst[(c4 + 3) * APAD + row] = v.w;
    }

    float o[4][4];
    float mrow[4], lrow[4];
#pragma unroll
    for (int i = 0; i < 4; ++i) {
        mrow[i] = -1e30f; lrow[i] = 0.f;
#pragma unroll
        for (int j = 0; j < 4; ++j) o[i][j] = 0.f;
    }

    const float scale = 0.125f;

    for (int kt = 0; kt <= qt; ++kt) {
        const float* Kb = g_K + ((size_t)bh * SEQ + kt * 64) * DH;
        const float* Vb = g_V + ((size_t)bh * SEQ + kt * 64) * DH;
#pragma unroll
        for (int r = 0; r < 4; ++r) {
            int row = r * 16 + ty;
            int c4  = tx * 4;
            float4 kv = *(const float4*)(Kb + row * DH + c4);
            Kst[(c4 + 0) * APAD + row] = kv.x;
            Kst[(c4 + 1) * APAD + row] = kv.y;
            Kst[(c4 + 2) * APAD + row] = kv.z;
            Kst[(c4 + 3) * APAD + row] = kv.w;
            float4 vv = *(const float4*)(Vb + row * DH + c4);
            *(float4*)&Vs[row * APAD + c4] = vv;
        }
        __syncthreads();

        float s[4][4];
#pragma unroll
        for (int i = 0; i < 4; ++i)
#pragma unroll
            for (int j = 0; j < 4; ++j) s[i][j] = 0.f;

#pragma unroll 8
        for (int d = 0; d < 64; ++d) {
            float4 qv = *(const float4*)&Qst[d * APAD + ty * 4];
            float4 kv = *(const float4*)&Kst[d * APAD + tx * 4];
            float qa[4] = {qv.x, qv.y, qv.z, qv.w};
            float ka[4] = {kv.x, kv.y, kv.z, kv.w};
#pragma unroll
            for (int i = 0; i < 4; ++i)
#pragma unroll
                for (int j = 0; j < 4; ++j)
                    s[i][j] = fmaf(qa[i], ka[j], s[i][j]);
        }

        if (kt == qt) {
#pragma unroll
            for (int i = 0; i < 4; ++i)
#pragma unroll
                for (int j = 0; j < 4; ++j)
                    s[i][j] = ((tx * 4 + j) > (ty * 4 + i)) ? -1e30f : s[i][j] * scale;
        } else {
#pragma unroll
            for (int i = 0; i < 4; ++i)
#pragma unroll
                for (int j = 0; j < 4; ++j) s[i][j] *= scale;
        }

        float p[4][4];
#pragma unroll
        for (int i = 0; i < 4; ++i) {
            float mt = s[i][0];
            mt = fmaxf(mt, s[i][1]); mt = fmaxf(mt, s[i][2]); mt = fmaxf(mt, s[i][3]);
#pragma unroll
            for (int off = 8; off >= 1; off >>= 1)
                mt = fmaxf(mt, __shfl_xor_sync(0xffffffffu, mt, off, 16));
            float mnew = fmaxf(mrow[i], mt);
            float alpha = __expf(mrow[i] - mnew);
            float lt = 0.f;
#pragma unroll
            for (int j = 0; j < 4; ++j) {
                p[i][j] = __expf(s[i][j] - mnew);
                lt += p[i][j];
            }
#pragma unroll
            for (int off = 8; off >= 1; off >>= 1)
                lt += __shfl_xor_sync(0xffffffffu, lt, off, 16);
            lrow[i] = lrow[i] * alpha + lt;
            mrow[i] = mnew;
#pragma unroll
            for (int j = 0; j < 4; ++j) o[i][j] *= alpha;
        }

#pragma unroll
        for (int i = 0; i < 4; ++i)
#pragma unroll
            for (int j = 0; j < 4; ++j)
                Pst[(tx * 4 + j) * APAD + ty * 4 + i] = p[i][j];
        __syncthreads();

#pragma unroll 8
        for (int k = 0; k < 64; ++k) {
            float4 pv = *(const float4*)&Pst[k * APAD + ty * 4];
            float4 vv = *(const float4*)&Vs[k * APAD + tx * 4];
            float pa[4] = {pv.x, pv.y, pv.z, pv.w};
            float va[4] = {vv.x, vv.y, vv.z, vv.w};
#pragma unroll
            for (int i = 0; i < 4; ++i)
#pragma unroll
                for (int j = 0; j < 4; ++j)
                    o[i][j] = fmaf(pa[i], va[j], o[i][j]);
        }
        __syncthreads();
    }

    int b = bh >> 4;
    int h = bh & 15;
#pragma unroll
    for (int i = 0; i < 4; ++i) {
        float inv = 1.f / lrow[i];
        int q = qt * 64 + ty * 4 + i;
        float4 v = make_float4(o[i][0] * inv, o[i][1] * inv, o[i][2] * inv, o[i][3] * inv);
        *(float4*)&g_T[((size_t)(b * SEQ + q)) * D_MODEL + h * 64 + tx * 4] = v;
    }
}

// ---------------------------------------------------------------------------
// Launch
// ---------------------------------------------------------------------------
extern "C" void kernel_launch(void* const* d_in, const int* in_sizes, int n_in,
                              void* d_out, int out_size)
{
    const float* X  = (const float*)d_in[0];
    const float* WQ = (const float*)d_in[1];
    const float* WK = (const float*)d_in[2];
    const float* WV = (const float*)d_in[3];
    const float* WO = (const float*)d_in[4];
    float* out = (float*)d_out;

    // fp32 -> bf16 hi/lo splits
    convert_split<<<2048, 256>>>(X,  MTOT * D_MODEL, 4);
    convert_split<<<1024, 256>>>(WQ, D_MODEL * D_MODEL, 0);
    convert_split<<<1024, 256>>>(WK, D_MODEL * D_MODEL, 1);
    convert_split<<<1024, 256>>>(WV, D_MODEL * D_MODEL, 2);
    convert_split<<<1024, 256>>>(WO, D_MODEL * D_MODEL, 3);

    cudaFuncSetAttribute(gemm_mma, cudaFuncAttributeMaxDynamicSharedMemorySize, GSM_BYTES);
    dim3 ggrid(D_MODEL / 128, MTOT / 128);   // (8, 64)
    gemm_mma<<<ggrid, 256, GSM_BYTES>>>(nullptr, 0);   // Q
    gemm_mma<<<ggrid, 256, GSM_BYTES>>>(nullptr, 1);   // K
    gemm_mma<<<ggrid, 256, GSM_BYTES>>>(nullptr, 2);   // V

    cudaFuncSetAttribute(attn_kernel, cudaFuncAttributeMaxDynamicSharedMemorySize, ASMEM_BYTES);
    dim3 agrid(SEQ / 64, BATCH * NHEAD);     // (32, 64)
    attn_kernel<<<agrid, 256, ASMEM_BYTES>>>();

    convert_split<<<2048, 256>>>(X /*unused*/, MTOT * D_MODEL, 5);  // g_T -> g_Text
    gemm_mma<<<ggrid, 256, GSM_BYTES>>>(out, 3);       // output projection
}